// round 8
// baseline (speedup 1.0000x reference)
#include <cuda_runtime.h>

// SmoothRankAP (quick_forward, sigmoid, tau=0.01), B=512. Single fused kernel.
// sigma(x) = 0.5*tanh(x/2)+0.5 with h = scores*50.
//   T_all(i) = sum_j tanh(h_j - h_i)        -> sim_all = 0.5*T_all + 256.5
//   T_pos(i) = sum_j tanh(h_j - h_i) * t_j  -> sim_pos = 0.5*(T_pos - tanh(h_q-h_i) + npos) + 0.5
//   ap[q] = (1/npos) * sum_{i: t=1} sim_pos/sim_all;  out = 1 - mean_q ap
//
// 512 blocks x 256 threads. Fully vectorized loads (float4 row cache, float2
// own-chunk), zero smem staging, one barrier, packed-int atomic tail.

static constexpr int BB = 512;

// [63:12] fixed-point ap-sum (scale 2^32), [11:0] arrival count (max 512).
__device__ unsigned long long g_accum = 0ull;

__device__ __forceinline__ float tanh_approx(float x) {
    float y;
    asm("tanh.approx.f32 %0, %1;" : "=f"(y) : "f"(x));
    return y;
}

__global__ __launch_bounds__(256) void smoothap_fused_kernel(
    const float* __restrict__ scores,
    const float* __restrict__ target,
    float* __restrict__ out)
{
    __shared__ float warp_acc[8];

    const int tid  = threadIdx.x;
    const int wid  = tid >> 5;        // 0..7
    const int lane = tid & 31;
    const int q    = blockIdx.x;

    const float* __restrict__ srow = scores + (size_t)q * BB;
    const float* __restrict__ trow = target + (size_t)q * BB;
    const float4* __restrict__ srow4 = reinterpret_cast<const float4*>(srow);
    const float4* __restrict__ trow4 = reinterpret_cast<const float4*>(trow);

    // ---- full-row register cache: 4 x LDG.128 each (lane covers cols 128k+4l..+3) ----
    float4 hv[4], tv[4];
    #pragma unroll
    for (int k = 0; k < 4; ++k) {
        float4 v = __ldg(srow4 + k * 32 + lane);
        hv[k] = make_float4(v.x * 50.0f, v.y * 50.0f, v.z * 50.0f, v.w * 50.0f);
        tv[k] = __ldg(trow4 + k * 32 + lane);
    }
    // own chunk: warp w owns cols [64w, 64w+64); lane l holds cols 64w+2l, +1
    const float2 so = __ldg(reinterpret_cast<const float2*>(srow + 64 * wid) + lane);
    const float2 to = __ldg(reinterpret_cast<const float2*>(trow + 64 * wid) + lane);
    const float hx = so.x * 50.0f, hy = so.y * 50.0f;
    const float hq = __ldg(srow + q) * 50.0f;            // broadcast load

    // npos = sum(target row): exact small integer
    float fnp;
    {
        float s = 0.0f;
        #pragma unroll
        for (int k = 0; k < 4; ++k)
            s += (tv[k].x + tv[k].y) + (tv[k].z + tv[k].w);
        #pragma unroll
        for (int o = 16; o; o >>= 1) s += __shfl_xor_sync(0xffffffffu, s, o);
        fnp = s;
    }

    // positive masks over own chunk: bit l of m0 -> col 64w+2l, of m1 -> col 64w+2l+1
    unsigned m0 = __ballot_sync(0xffffffffu, to.x > 0.5f);
    unsigned m1 = __ballot_sync(0xffffffffu, to.y > 0.5f);
    unsigned long long mm = ((unsigned long long)m1 << 32) | (unsigned long long)m0;

    // ---- enumerate own positive pairs, two at a time (fixed order -> deterministic) ----
    float acc = 0.0f;   // uniform across lanes after xor-reduces
    while (mm) {
        const int b0 = __ffsll(mm) - 1;  mm &= mm - 1;
        const bool two = (mm != 0ull);
        int b1 = b0;
        if (two) { b1 = __ffsll(mm) - 1; mm &= mm - 1; }

        // broadcast h_i from own-chunk registers
        const float x0 = __shfl_sync(0xffffffffu, hx, b0 & 31);
        const float y0 = __shfl_sync(0xffffffffu, hy, b0 & 31);
        const float hiA = (b0 < 32) ? x0 : y0;
        const float x1 = __shfl_sync(0xffffffffu, hx, b1 & 31);
        const float y1 = __shfl_sync(0xffffffffu, hy, b1 & 31);
        const float hiB = (b1 < 32) ? x1 : y1;

        float aA = 0.0f, pA = 0.0f, aB = 0.0f, pB = 0.0f;
        #pragma unroll
        for (int k = 0; k < 4; ++k) {
            #define SRA_STEP(H, T)                                   \
                { const float thA = tanh_approx((H) - hiA);          \
                  const float thB = tanh_approx((H) - hiB);          \
                  aA += thA; pA = fmaf(thA, (T), pA);                \
                  aB += thB; pB = fmaf(thB, (T), pB); }
            SRA_STEP(hv[k].x, tv[k].x)
            SRA_STEP(hv[k].y, tv[k].y)
            SRA_STEP(hv[k].z, tv[k].z)
            SRA_STEP(hv[k].w, tv[k].w)
            #undef SRA_STEP
        }
        #pragma unroll
        for (int o = 16; o; o >>= 1) {
            aA += __shfl_xor_sync(0xffffffffu, aA, o);
            pA += __shfl_xor_sync(0xffffffffu, pA, o);
            aB += __shfl_xor_sync(0xffffffffu, aB, o);
            pB += __shfl_xor_sync(0xffffffffu, pB, o);
        }
        const float thqA = tanh_approx(hq - hiA);
        acc += __fdividef(0.5f * (pA - thqA + fnp) + 0.5f, 0.5f * aA + 256.5f);
        if (two) {
            const float thqB = tanh_approx(hq - hiB);
            acc += __fdividef(0.5f * (pB - thqB + fnp) + 0.5f, 0.5f * aB + 256.5f);
        }
    }

    if (lane == 0) warp_acc[wid] = acc;
    __syncthreads();                    // the ONLY block-wide sync

    if (tid == 0) {
        float g = ((warp_acc[0] + warp_acc[1]) + (warp_acc[2] + warp_acc[3]))
                + ((warp_acc[4] + warp_acc[5]) + (warp_acc[6] + warp_acc[7]));
        const float ap = __fdividef(g, fnp);          // ap in [0,1]

        // fixed-point (scale 2^32) + count in low 12 bits; integer sum -> deterministic
        unsigned long long contrib =
            ((unsigned long long)__float2ull_rn(ap * 4294967296.0f) << 12) | 1ull;
        unsigned long long nv = atomicAdd(&g_accum, contrib) + contrib;

        if ((nv & 0xFFFull) == (unsigned long long)BB) {      // I'm the last block
            const double sum_ap = (double)(nv >> 12) * (1.0 / 4294967296.0);
            out[0] = (float)(1.0 - sum_ap * (1.0 / (double)BB));
            atomicExch(&g_accum, 0ull);                       // reset for next replay
        }
    }
}

extern "C" void kernel_launch(void* const* d_in, const int* in_sizes, int n_in,
                              void* d_out, int out_size)
{
    const float* scores = (const float*)d_in[0];
    const float* target = (const float*)d_in[1];
    smoothap_fused_kernel<<<BB, 256>>>(scores, target, (float*)d_out);
}

// round 9
// speedup vs baseline: 1.0469x; 1.0469x over previous
#include <cuda_runtime.h>

// SmoothRankAP (quick_forward, sigmoid, tau=0.01), B=512. Single fused kernel.
// sigma(x) = 0.5*tanh(x/2)+0.5 with h = scores*50.
//   T_all(i) = sum_j tanh(h_j - h_i)        -> sim_all = 0.5*T_all + 256.5
//   T_pos(i) = sum_j tanh(h_j - h_i) * t_j  -> sim_pos = 0.5*(T_pos - tanh(h_q-h_i) + npos) + 0.5
//   ap[q] = (1/npos) * sum_{i: t=1} sim_pos/sim_all;  out = 1 - mean_q ap
//
// 512 blocks x 256 threads, ZERO barriers / ZERO smem: every warp is fully
// autonomous and contributes acc_warp/npos straight into one packed
// fixed-point atomic (deterministic integer sum). Warp count field = 13 bits.

static constexpr int BB = 512;
static constexpr unsigned long long NWARPS_TOTAL = (unsigned long long)BB * 8ull; // 4096

// [63:13] fixed-point ap-sum (scale 2^32), [12:0] arrival count (max 4096).
__device__ unsigned long long g_accum = 0ull;

__device__ __forceinline__ float tanh_approx(float x) {
    float y;
    asm("tanh.approx.f32 %0, %1;" : "=f"(y) : "f"(x));
    return y;
}

__global__ __launch_bounds__(256) void smoothap_fused_kernel(
    const float* __restrict__ scores,
    const float* __restrict__ target,
    float* __restrict__ out)
{
    const int tid  = threadIdx.x;
    const int wid  = tid >> 5;        // 0..7
    const int lane = tid & 31;
    const int q    = blockIdx.x;

    const float* __restrict__ srow = scores + (size_t)q * BB;
    const float* __restrict__ trow = target + (size_t)q * BB;

    // own chunk first (warp w owns cols [64w,64w+64); lane l -> cols 64w+2l,+1)
    const float2 so = __ldg(reinterpret_cast<const float2*>(srow + 64 * wid) + lane);
    const float2 to = __ldg(reinterpret_cast<const float2*>(trow + 64 * wid) + lane);
    const float hx = so.x * 50.0f, hy = so.y * 50.0f;

    // full-row register cache: 4 x LDG.128 each (lane covers cols 128k+4l..+3)
    const float4* __restrict__ srow4 = reinterpret_cast<const float4*>(srow);
    const float4* __restrict__ trow4 = reinterpret_cast<const float4*>(trow);
    float4 hv[4], tv[4];
    #pragma unroll
    for (int k = 0; k < 4; ++k) {
        float4 v = __ldg(srow4 + k * 32 + lane);
        hv[k] = make_float4(v.x * 50.0f, v.y * 50.0f, v.z * 50.0f, v.w * 50.0f);
        tv[k] = __ldg(trow4 + k * 32 + lane);
    }
    const float hq = __ldg(srow + q) * 50.0f;            // broadcast load

    // npos via ballot+popc: uniform integer, no shuffle chain
    int np = 0;
    #pragma unroll
    for (int k = 0; k < 4; ++k) {
        np += __popc(__ballot_sync(0xffffffffu, tv[k].x > 0.5f));
        np += __popc(__ballot_sync(0xffffffffu, tv[k].y > 0.5f));
        np += __popc(__ballot_sync(0xffffffffu, tv[k].z > 0.5f));
        np += __popc(__ballot_sync(0xffffffffu, tv[k].w > 0.5f));
    }
    const float fnp = (float)np;      // >= 1 (diagonal always positive)

    // positive masks over own chunk
    unsigned m0 = __ballot_sync(0xffffffffu, to.x > 0.5f);
    unsigned m1 = __ballot_sync(0xffffffffu, to.y > 0.5f);
    unsigned long long mm = ((unsigned long long)m1 << 32) | (unsigned long long)m0;

    // ---- enumerate own positive pairs, two at a time (fixed order -> deterministic) ----
    float acc = 0.0f;   // uniform across lanes after xor-reduces
    while (mm) {
        const int b0 = __ffsll(mm) - 1;  mm &= mm - 1;
        const bool two = (mm != 0ull);
        int b1 = b0;
        if (two) { b1 = __ffsll(mm) - 1; mm &= mm - 1; }

        const float x0 = __shfl_sync(0xffffffffu, hx, b0 & 31);
        const float y0 = __shfl_sync(0xffffffffu, hy, b0 & 31);
        const float hiA = (b0 < 32) ? x0 : y0;
        const float x1 = __shfl_sync(0xffffffffu, hx, b1 & 31);
        const float y1 = __shfl_sync(0xffffffffu, hy, b1 & 31);
        const float hiB = (b1 < 32) ? x1 : y1;

        float aA = 0.0f, pA = 0.0f, aB = 0.0f, pB = 0.0f;
        #pragma unroll
        for (int k = 0; k < 4; ++k) {
            #define SRA_STEP(H, T)                                   \
                { const float thA = tanh_approx((H) - hiA);          \
                  const float thB = tanh_approx((H) - hiB);          \
                  aA += thA; pA = fmaf(thA, (T), pA);                \
                  aB += thB; pB = fmaf(thB, (T), pB); }
            SRA_STEP(hv[k].x, tv[k].x)
            SRA_STEP(hv[k].y, tv[k].y)
            SRA_STEP(hv[k].z, tv[k].z)
            SRA_STEP(hv[k].w, tv[k].w)
            #undef SRA_STEP
        }
        #pragma unroll
        for (int o = 16; o; o >>= 1) {
            aA += __shfl_xor_sync(0xffffffffu, aA, o);
            pA += __shfl_xor_sync(0xffffffffu, pA, o);
            aB += __shfl_xor_sync(0xffffffffu, aB, o);
            pB += __shfl_xor_sync(0xffffffffu, pB, o);
        }
        const float thqA = tanh_approx(hq - hiA);
        acc += __fdividef(0.5f * (pA - thqA + fnp) + 0.5f, 0.5f * aA + 256.5f);
        if (two) {
            const float thqB = tanh_approx(hq - hiB);
            acc += __fdividef(0.5f * (pB - thqB + fnp) + 0.5f, 0.5f * aB + 256.5f);
        }
    }

    // ---- per-warp autonomous finish: one packed atomic, no barrier ----
    if (lane == 0) {
        const float w_ap = __fdividef(acc, fnp);   // this warp's share of ap[q], in [0,1]
        unsigned long long contrib =
            ((unsigned long long)__float2ull_rn(w_ap * 4294967296.0f) << 13) | 1ull;
        unsigned long long nv = atomicAdd(&g_accum, contrib) + contrib;

        if ((nv & 0x1FFFull) == NWARPS_TOTAL) {    // unique last-arriving warp
            const double sum_ap = (double)(nv >> 13) * (1.0 / 4294967296.0);
            out[0] = (float)(1.0 - sum_ap * (1.0 / (double)BB));
            atomicExch(&g_accum, 0ull);            // reset for next graph replay
        }
    }
}

extern "C" void kernel_launch(void* const* d_in, const int* in_sizes, int n_in,
                              void* d_out, int out_size)
{
    const float* scores = (const float*)d_in[0];
    const float* target = (const float*)d_in[1];
    smoothap_fused_kernel<<<BB, 256>>>(scores, target, (float*)d_out);
}